// round 2
// baseline (speedup 1.0000x reference)
#include <cuda_runtime.h>
#include <math.h>

#define M_ROWS  131072
#define N_CODES 2048
#define K_DIM   256
#define BM 128
#define BN 128
#define BK 16
#define TM 8
#define TN 8

// Output layout (flattened tuple, fp32):
// [0] loss, [1 .. 1+M*K) quantized_st, [OFF_PERP] perplexity, [OFF_ENC ..) encodings
#define OFF_Q    1
#define OFF_PERP 33554433
#define OFF_ENC  33554434

#define EPI_BLOCKS (M_ROWS / 8)

// -------- device scratch (no allocations allowed) --------
__device__ int    g_indices[M_ROWS];
__device__ int    g_hist[N_CODES];
__device__ float  g_cbnorm[N_CODES];
__device__ float  g_xnorm[M_ROWS];
__device__ double g_part[EPI_BLOCKS];

// ============================================================
// Kernel 1: codebook squared norms (EMULATES reference rounding:
// squares rounded individually, then scalar-sequential sum) + zero hist.
// One thread per code.
// ============================================================
__global__ void vq_init(const float* __restrict__ CB) {
    int gid = blockIdx.x * blockDim.x + threadIdx.x;
    if (gid < N_CODES) {
        const float* row = CB + (long)gid * K_DIM;
        float s = 0.f;
        for (int k = 0; k < K_DIM; k++) {
            float v = row[k];
            s = __fadd_rn(s, __fmul_rn(v, v));   // NO fma contraction
        }
        g_cbnorm[gid] = s;
        g_hist[gid] = 0;
    }
}

// ============================================================
// Kernel 1b: per-row ||x||^2, scalar-sequential emulation.
// Block = 256 rows; stage 32-col chunks via shared for coalescing,
// each thread owns one row and accumulates sequentially k ascending.
// ============================================================
__global__ void vq_xnorm(const float* __restrict__ X) {
    __shared__ float sh[256][33];
    const int tid = threadIdx.x;
    const long r0 = (long)blockIdx.x * 256;
    float acc = 0.f;
    for (int c0 = 0; c0 < K_DIM; c0 += 32) {
        // cooperative coalesced load of [256 rows x 32 cols]
        for (int idx = tid; idx < 256 * 32; idx += 256) {
            int row = idx >> 5, col = idx & 31;
            sh[row][col] = X[(r0 + row) * K_DIM + c0 + col];
        }
        __syncthreads();
#pragma unroll
        for (int c = 0; c < 32; c++) {
            float v = sh[tid][c];
            acc = __fadd_rn(acc, __fmul_rn(v, v));  // sequential, no FMA
        }
        __syncthreads();
    }
    g_xnorm[r0 + tid] = acc;
}

// ============================================================
// Kernel 2: fused GEMM + argmin.
// m = x.e accumulated as ONE sequential fmaf chain, k ascending
// (matches Eigen-NEON gebp / cuBLAS SGEMM single-accumulator order).
// Distance EMULATES the reference formula's fp32 rounding:
//   d = fl( fl(xn + en) - fl(2*m) )
// The coarse quantization at ~256 magnitude creates exact ties;
// argmin tie-break = lowest index (reference argmin = first occurrence).
// ============================================================
__global__ void __launch_bounds__(256, 2)
vq_gemm_argmin(const float* __restrict__ X, const float* __restrict__ CB) {
    __shared__ float As[BK][BM];
    __shared__ float Bs[BK][BN];
    __shared__ float rv[BM][16];
    __shared__ int   ri[BM][16];

    const int tid = threadIdx.x;
    const int tx = tid & 15;   // code direction (8 codes each)
    const int ty = tid >> 4;   // row direction (8 rows each)
    const long row0 = (long)blockIdx.x * BM;
    const float* Xblk = X + row0 * K_DIM;

    const int lrow = tid >> 2;        // 0..63
    const int lcol = (tid & 3) << 2;  // 0,4,8,12

    float xnr[TM];
#pragma unroll
    for (int i = 0; i < TM; i++) xnr[i] = g_xnorm[row0 + ty * 8 + i];

    float minv[TM];
    int   mini[TM];
#pragma unroll
    for (int i = 0; i < TM; i++) { minv[i] = INFINITY; mini[i] = 0x7fffffff; }

    for (int nt = 0; nt < N_CODES / BN; ++nt) {
        const float* Bblk = CB + (long)nt * BN * K_DIM;
        float acc[TM][TN];
#pragma unroll
        for (int i = 0; i < TM; i++)
#pragma unroll
            for (int j = 0; j < TN; j++) acc[i][j] = 0.f;

        for (int kk = 0; kk < K_DIM; kk += BK) {
#pragma unroll
            for (int r = 0; r < 2; r++) {
                int row = lrow + 64 * r;
                float4 va = *reinterpret_cast<const float4*>(
                    Xblk + (long)row * K_DIM + kk + lcol);
                As[lcol + 0][row] = va.x;
                As[lcol + 1][row] = va.y;
                As[lcol + 2][row] = va.z;
                As[lcol + 3][row] = va.w;
                float4 vb = *reinterpret_cast<const float4*>(
                    Bblk + (long)row * K_DIM + kk + lcol);
                Bs[lcol + 0][row] = vb.x;
                Bs[lcol + 1][row] = vb.y;
                Bs[lcol + 2][row] = vb.z;
                Bs[lcol + 3][row] = vb.w;
            }
            __syncthreads();
#pragma unroll
            for (int k = 0; k < BK; k++) {
                float4 a0 = *reinterpret_cast<const float4*>(&As[k][ty * 8]);
                float4 a1 = *reinterpret_cast<const float4*>(&As[k][ty * 8 + 4]);
                float4 b0 = *reinterpret_cast<const float4*>(&Bs[k][tx * 8]);
                float4 b1 = *reinterpret_cast<const float4*>(&Bs[k][tx * 8 + 4]);
                float av[TM] = {a0.x, a0.y, a0.z, a0.w, a1.x, a1.y, a1.z, a1.w};
                float bv[TN] = {b0.x, b0.y, b0.z, b0.w, b1.x, b1.y, b1.z, b1.w};
#pragma unroll
                for (int i = 0; i < TM; i++)
#pragma unroll
                    for (int j = 0; j < TN; j++)
                        acc[i][j] = fmaf(av[i], bv[j], acc[i][j]);
            }
            __syncthreads();
        }
        // quantized-distance argmin update for this 128-code tile
#pragma unroll
        for (int j = 0; j < TN; j++) {
            int code = nt * BN + tx * 8 + j;
            float cn = g_cbnorm[code];
#pragma unroll
            for (int i = 0; i < TM; i++) {
                float s = __fsub_rn(__fadd_rn(xnr[i], cn),
                                    __fmul_rn(2.f, acc[i][j]));
                if (s < minv[i]) { minv[i] = s; mini[i] = code; }
            }
        }
    }

    // cross-thread (16 code-lanes) reduction per row, lowest-index ties
#pragma unroll
    for (int i = 0; i < TM; i++) {
        rv[ty * 8 + i][tx] = minv[i];
        ri[ty * 8 + i][tx] = mini[i];
    }
    __syncthreads();
    if (tid < BM) {
        float bvv = rv[tid][0];
        int   bii = ri[tid][0];
#pragma unroll
        for (int t = 1; t < 16; t++) {
            float v = rv[tid][t];
            int   ix = ri[tid][t];
            if (v < bvv || (v == bvv && ix < bii)) { bvv = v; bii = ix; }
        }
        g_indices[row0 + tid] = bii;
    }
}

// ============================================================
// Kernel 3: epilogue. One warp per row.
//  - gather quantized = codebook[idx] -> out
//  - write one-hot encodings row (zeros + single 1.0, single pass)
//  - histogram count (int atomics, deterministic)
//  - per-block SSE partial (fixed-order reduction, deterministic)
// ============================================================
__global__ void vq_epilogue(const float* __restrict__ X,
                            const float* __restrict__ CB,
                            float* __restrict__ out) {
    __shared__ float warp_sse[8];
    const int wid  = threadIdx.x >> 5;
    const int lane = threadIdx.x & 31;
    const long row = (long)blockIdx.x * 8 + wid;
    const int idx = g_indices[row];

    const float4* xr = reinterpret_cast<const float4*>(X + row * K_DIM);
    const float4* cr = reinterpret_cast<const float4*>(CB + (long)idx * K_DIM);
    float* q = out + OFF_Q + row * K_DIM;

    float sse = 0.f;
#pragma unroll
    for (int t = 0; t < 2; t++) {
        int c4 = lane + 32 * t;
        float4 xv = xr[c4];
        float4 cv = cr[c4];
        q[c4 * 4 + 0] = cv.x;
        q[c4 * 4 + 1] = cv.y;
        q[c4 * 4 + 2] = cv.z;
        q[c4 * 4 + 3] = cv.w;
        float d0 = cv.x - xv.x, d1 = cv.y - xv.y;
        float d2 = cv.z - xv.z, d3 = cv.w - xv.w;
        sse += d0 * d0 + d1 * d1 + d2 * d2 + d3 * d3;
    }

    // encodings row: base offset is 8B-aligned (OFF_ENC even), use float2
    float2* enc = reinterpret_cast<float2*>(out + OFF_ENC + row * (long)N_CODES);
    const int hot_chunk = idx >> 1;
#pragma unroll
    for (int t = 0; t < 32; t++) {
        int c = lane + 32 * t;
        float2 v = make_float2(0.f, 0.f);
        if (c == hot_chunk) { if (idx & 1) v.y = 1.f; else v.x = 1.f; }
        enc[c] = v;
    }

#pragma unroll
    for (int o = 16; o; o >>= 1) sse += __shfl_xor_sync(0xffffffffu, sse, o);
    if (lane == 0) {
        atomicAdd(&g_hist[idx], 1);
        warp_sse[wid] = sse;
    }
    __syncthreads();
    if (threadIdx.x == 0) {
        double s = 0.0;
        for (int w = 0; w < 8; w++) s += (double)warp_sse[w];
        g_part[blockIdx.x] = s;
    }
}

// ============================================================
// Kernel 4: finalize loss + perplexity (1 block, deterministic)
// ============================================================
__global__ void vq_finalize(float* __restrict__ out) {
    __shared__ double sh[256];
    __shared__ double sh2[256];
    const int tid = threadIdx.x;

    double s = 0.0;
    for (int i = tid; i < EPI_BLOCKS; i += 256) s += g_part[i];
    sh[tid] = s;

    double ent = 0.0;
    for (int i = tid; i < N_CODES; i += 256) {
        double p = (double)g_hist[i] * (1.0 / (double)M_ROWS);
        ent -= p * log(p + 1e-10);
    }
    sh2[tid] = ent;
    __syncthreads();

    for (int st = 128; st; st >>= 1) {
        if (tid < st) { sh[tid] += sh[tid + st]; sh2[tid] += sh2[tid + st]; }
        __syncthreads();
    }
    if (tid == 0) {
        double mse = sh[0] / ((double)M_ROWS * (double)K_DIM);
        out[0]        = (float)(1.25 * mse);
        out[OFF_PERP] = (float)exp(sh2[0]);
    }
}

// ============================================================
extern "C" void kernel_launch(void* const* d_in, const int* in_sizes, int n_in,
                              void* d_out, int out_size) {
    const float* X  = (const float*)d_in[0];
    const float* CB = (const float*)d_in[1];
    float* out = (float*)d_out;

    vq_init<<<8, 256>>>(CB);
    vq_xnorm<<<M_ROWS / 256, 256>>>(X);
    vq_gemm_argmin<<<M_ROWS / BM, 256>>>(X, CB);
    vq_epilogue<<<EPI_BLOCKS, 256>>>(X, CB, out);
    vq_finalize<<<1, 256>>>(out);
}

// round 3
// speedup vs baseline: 1.0051x; 1.0051x over previous
#include <cuda_runtime.h>
#include <cuda_bf16.h>
#include <math.h>

#define M_ROWS  131072
#define N_CODES 2048
#define K_DIM   256

#define OFF_Q    1
#define OFF_PERP 33554433
#define OFF_ENC  33554434

#define EPI_BLOCKS (M_ROWS / 8)

#define CAP     16
#define MARGIN  2.5e-3f
#define PITCH   264   // bf16 elements per smem row (256 + 8 pad)

// -------- device scratch --------
__device__ int            g_indices[M_ROWS];
__device__ int            g_hist[N_CODES];
__device__ float          g_cbnorm[N_CODES];
__device__ float          g_xnorm[M_ROWS];
__device__ double         g_part[EPI_BLOCKS];
__device__ __nv_bfloat16  g_cbbf[N_CODES * K_DIM];
__device__ int            g_ccnt[M_ROWS];
__device__ int            g_cand[M_ROWS * CAP];

// ============================================================
// Kernel 1: exact codebook norms (reference fp32 rounding emulation),
// bf16 copy of codebook, zero histogram. One thread per code.
// ============================================================
__global__ void vq_init(const float* __restrict__ CB) {
    int gid = blockIdx.x * blockDim.x + threadIdx.x;
    if (gid < N_CODES) {
        const float* row = CB + (long)gid * K_DIM;
        float s = 0.f;
        for (int k = 0; k < K_DIM; k++) {
            float v = row[k];
            s = __fadd_rn(s, __fmul_rn(v, v));   // no FMA contraction
            g_cbbf[(long)gid * K_DIM + k] = __float2bfloat16_rn(v);
        }
        g_cbnorm[gid] = s;
        g_hist[gid] = 0;
    }
}

// ============================================================
// Kernel 1b: per-row ||x||^2 exact scalar-sequential emulation,
// plus candidate-counter zeroing.
// ============================================================
__global__ void vq_xnorm(const float* __restrict__ X) {
    __shared__ float sh[256][33];
    const int tid = threadIdx.x;
    const long r0 = (long)blockIdx.x * 256;
    float acc = 0.f;
    for (int c0 = 0; c0 < K_DIM; c0 += 32) {
        for (int idx = tid; idx < 256 * 32; idx += 256) {
            int row = idx >> 5, col = idx & 31;
            sh[row][col] = X[(r0 + row) * K_DIM + c0 + col];
        }
        __syncthreads();
#pragma unroll
        for (int c = 0; c < 32; c++) {
            float v = sh[tid][c];
            acc = __fadd_rn(acc, __fmul_rn(v, v));
        }
        __syncthreads();
    }
    g_xnorm[r0 + tid] = acc;
    g_ccnt[r0 + tid] = 0;
}

// ============================================================
// Kernel 2 (phase 1): bf16 tensor-core GEMM producing approximate
// scores s~ = ||e||^2 - 2 x.e (+4 shift for monotone uint compare).
// Per-row running min (packed u64 key: float bits << 32 | code) and
// conservative candidate collection within MARGIN of the running min.
// Block: 256 thr = 8 warps (2 row x 4 code), tile 128 rows x 128 codes,
// full K=256 resident in dynamic smem. 16 code tiles sweep all codes.
// ============================================================
__global__ void __launch_bounds__(256)
vq_phase1(const float* __restrict__ X) {
    extern __shared__ unsigned char smem_raw[];
    __nv_bfloat16* Xs = (__nv_bfloat16*)smem_raw;                 // 128 x PITCH
    __nv_bfloat16* Bs = Xs + 128 * PITCH;                         // 128 x PITCH
    unsigned long long* rmin = (unsigned long long*)(Bs + 128 * PITCH); // 128

    const int tid  = threadIdx.x;
    const int lane = tid & 31;
    const int wid  = tid >> 5;
    const int warp_r = wid >> 2;   // 0..1
    const int warp_c = wid & 3;    // 0..3
    const long row0 = (long)blockIdx.x * 128;

    // load X block (fp32) and convert to bf16 in smem
    for (int i = tid; i < 128 * 64; i += 256) {
        int row = i >> 6, seg = i & 63;
        float4 v = *(const float4*)(X + (row0 + row) * K_DIM + seg * 4);
        *(__nv_bfloat162*)(Xs + row * PITCH + seg * 4)     = __floats2bfloat162_rn(v.x, v.y);
        *(__nv_bfloat162*)(Xs + row * PITCH + seg * 4 + 2) = __floats2bfloat162_rn(v.z, v.w);
    }
    if (tid < 128) rmin[tid] = 0xFFFFFFFFFFFFFFFFULL;
    __syncthreads();

    const int rbase = warp_r * 64 + (lane >> 2);
    const int cbase = warp_c * 32 + 2 * (lane & 3);

    for (int nt = 0; nt < N_CODES / 128; nt++) {
        // load codebook tile (bf16, pre-converted)
        for (int i = tid; i < 128 * 32; i += 256) {
            int row = i >> 5, seg = i & 31;
            uint4 v = *(const uint4*)(g_cbbf + ((long)(nt * 128 + row)) * K_DIM + seg * 8);
            *(uint4*)(Bs + row * PITCH + seg * 8) = v;
        }
        __syncthreads();

        float acc[4][4][4];
#pragma unroll
        for (int mt = 0; mt < 4; mt++)
#pragma unroll
            for (int ntl = 0; ntl < 4; ntl++)
#pragma unroll
                for (int r = 0; r < 4; r++) acc[mt][ntl][r] = 0.f;

        for (int kk = 0; kk < K_DIM; kk += 16) {
            unsigned a[4][4], b[4][2];
            const int kcol = kk + 2 * (lane & 3);
#pragma unroll
            for (int mt = 0; mt < 4; mt++) {
                const __nv_bfloat16* base = Xs + (rbase + mt * 16) * PITCH + kcol;
                a[mt][0] = *(const unsigned*)(base);
                a[mt][1] = *(const unsigned*)(base + 8 * PITCH);
                a[mt][2] = *(const unsigned*)(base + 8);
                a[mt][3] = *(const unsigned*)(base + 8 * PITCH + 8);
            }
            const int bq = warp_c * 32 + (lane >> 2);
#pragma unroll
            for (int ntl = 0; ntl < 4; ntl++) {
                const __nv_bfloat16* base = Bs + (bq + ntl * 8) * PITCH + kcol;
                b[ntl][0] = *(const unsigned*)(base);
                b[ntl][1] = *(const unsigned*)(base + 8);
            }
#pragma unroll
            for (int mt = 0; mt < 4; mt++)
#pragma unroll
                for (int ntl = 0; ntl < 4; ntl++)
                    asm volatile(
                        "mma.sync.aligned.m16n8k16.row.col.f32.bf16.bf16.f32 "
                        "{%0,%1,%2,%3}, {%4,%5,%6,%7}, {%8,%9}, {%0,%1,%2,%3};"
                        : "+f"(acc[mt][ntl][0]), "+f"(acc[mt][ntl][1]),
                          "+f"(acc[mt][ntl][2]), "+f"(acc[mt][ntl][3])
                        : "r"(a[mt][0]), "r"(a[mt][1]), "r"(a[mt][2]), "r"(a[mt][3]),
                          "r"(b[ntl][0]), "r"(b[ntl][1]));
        }

        // per-tile score + running-min update (shifted by +4 so all positive)
#pragma unroll
        for (int mt = 0; mt < 4; mt++)
#pragma unroll
            for (int h = 0; h < 2; h++) {
                int lrow = rbase + mt * 16 + 8 * h;
                unsigned long long best = 0xFFFFFFFFFFFFFFFFULL;
#pragma unroll
                for (int ntl = 0; ntl < 4; ntl++)
#pragma unroll
                    for (int c = 0; c < 2; c++) {
                        int code = nt * 128 + cbase + ntl * 8 + c;
                        float s = fmaf(-2.f, acc[mt][ntl][h * 2 + c],
                                       g_cbnorm[code]) + 4.0f;
                        acc[mt][ntl][h * 2 + c] = s;  // keep for pass 2
                        unsigned long long key =
                            ((unsigned long long)__float_as_uint(s) << 32) |
                            (unsigned)code;
                        if (key < best) best = key;
                    }
                atomicMin(&rmin[lrow], best);
            }
        __syncthreads();

        // candidate append vs running min (conservative superset)
#pragma unroll
        for (int mt = 0; mt < 4; mt++)
#pragma unroll
            for (int h = 0; h < 2; h++) {
                int lrow = rbase + mt * 16 + 8 * h;
                float thr = __uint_as_float((unsigned)(rmin[lrow] >> 32)) + MARGIN;
#pragma unroll
                for (int ntl = 0; ntl < 4; ntl++)
#pragma unroll
                    for (int c = 0; c < 2; c++) {
                        float s = acc[mt][ntl][h * 2 + c];
                        if (s <= thr) {
                            int code = nt * 128 + cbase + ntl * 8 + c;
                            long grow = row0 + lrow;
                            int pos = atomicAdd(&g_ccnt[grow], 1);
                            if (pos < CAP) g_cand[grow * CAP + pos] = code;
                        }
                    }
            }
        __syncthreads();
    }
}

// ============================================================
// Kernel 3 (phase 2): exact rescoring of candidates.
// Reproduces the reference fp32 rounding: m = sequential fmaf chain
// (k ascending), d = fl(fl(xn+cn) - fl(2m)), lowest-index tie-break.
// One warp per row; lane i handles candidate i. Overflow/empty ->
// full 2048-code exact scan (correctness fallback).
// ============================================================
__device__ __forceinline__ float exact_dist(const float* __restrict__ xr,
                                            const float* __restrict__ er,
                                            float xn, float cn) {
    float m = 0.f;
#pragma unroll 8
    for (int k = 0; k < K_DIM; k += 4) {
        float4 xv = *(const float4*)(xr + k);
        float4 ev = *(const float4*)(er + k);
        m = fmaf(xv.x, ev.x, m);
        m = fmaf(xv.y, ev.y, m);
        m = fmaf(xv.z, ev.z, m);
        m = fmaf(xv.w, ev.w, m);
    }
    return __fsub_rn(__fadd_rn(xn, cn), __fmul_rn(2.f, m));
}

__global__ void vq_phase2(const float* __restrict__ X,
                          const float* __restrict__ CB) {
    const int wid  = threadIdx.x >> 5;
    const int lane = threadIdx.x & 31;
    const long row = (long)blockIdx.x * 8 + wid;
    const int cnt = g_ccnt[row];
    const float xn = g_xnorm[row];
    const float* xr = X + row * K_DIM;

    unsigned long long key = 0xFFFFFFFFFFFFFFFFULL;
    if (cnt >= 1 && cnt <= CAP) {
        if (lane < cnt) {
            int code = g_cand[row * CAP + lane];
            float d = exact_dist(xr, CB + (long)code * K_DIM, xn, g_cbnorm[code]);
            key = ((unsigned long long)__float_as_uint(d) << 32) | (unsigned)code;
        }
    } else {
        for (int code = lane; code < N_CODES; code += 32) {
            float d = exact_dist(xr, CB + (long)code * K_DIM, xn, g_cbnorm[code]);
            unsigned long long k2 =
                ((unsigned long long)__float_as_uint(d) << 32) | (unsigned)code;
            if (k2 < key) key = k2;
        }
    }
#pragma unroll
    for (int o = 16; o; o >>= 1) {
        unsigned long long other = __shfl_xor_sync(0xffffffffu, key, o);
        if (other < key) key = other;
    }
    if (lane == 0) g_indices[row] = (int)(key & 0xFFFFFFFFu);
}

// ============================================================
// Kernel 4: epilogue. One warp per row.
//  - quantized_st = fl(x + fl(q - x))  (exact ST emulation)
//  - one-hot encodings row in a single pass
//  - histogram + per-block SSE partial (deterministic)
// ============================================================
__global__ void vq_epilogue(const float* __restrict__ X,
                            const float* __restrict__ CB,
                            float* __restrict__ out) {
    __shared__ float warp_sse[8];
    const int wid  = threadIdx.x >> 5;
    const int lane = threadIdx.x & 31;
    const long row = (long)blockIdx.x * 8 + wid;
    const int idx = g_indices[row];

    const float4* xr = reinterpret_cast<const float4*>(X + row * K_DIM);
    const float4* cr = reinterpret_cast<const float4*>(CB + (long)idx * K_DIM);
    float* q = out + OFF_Q + row * K_DIM;

    float sse = 0.f;
#pragma unroll
    for (int t = 0; t < 2; t++) {
        int c4 = lane + 32 * t;
        float4 xv = xr[c4];
        float4 cv = cr[c4];
        float d0 = __fsub_rn(cv.x, xv.x);
        float d1 = __fsub_rn(cv.y, xv.y);
        float d2 = __fsub_rn(cv.z, xv.z);
        float d3 = __fsub_rn(cv.w, xv.w);
        q[c4 * 4 + 0] = __fadd_rn(xv.x, d0);
        q[c4 * 4 + 1] = __fadd_rn(xv.y, d1);
        q[c4 * 4 + 2] = __fadd_rn(xv.z, d2);
        q[c4 * 4 + 3] = __fadd_rn(xv.w, d3);
        sse += d0 * d0 + d1 * d1 + d2 * d2 + d3 * d3;
    }

    float2* enc = reinterpret_cast<float2*>(out + OFF_ENC + row * (long)N_CODES);
    const int hot_chunk = idx >> 1;
#pragma unroll
    for (int t = 0; t < 32; t++) {
        int c = lane + 32 * t;
        float2 v = make_float2(0.f, 0.f);
        if (c == hot_chunk) { if (idx & 1) v.y = 1.f; else v.x = 1.f; }
        enc[c] = v;
    }

#pragma unroll
    for (int o = 16; o; o >>= 1) sse += __shfl_xor_sync(0xffffffffu, sse, o);
    if (lane == 0) {
        atomicAdd(&g_hist[idx], 1);
        warp_sse[wid] = sse;
    }
    __syncthreads();
    if (threadIdx.x == 0) {
        double s = 0.0;
        for (int w = 0; w < 8; w++) s += (double)warp_sse[w];
        g_part[blockIdx.x] = s;
    }
}

// ============================================================
// Kernel 5: finalize loss + perplexity (1 block, deterministic)
// ============================================================
__global__ void vq_finalize(float* __restrict__ out) {
    __shared__ double sh[256];
    __shared__ double sh2[256];
    const int tid = threadIdx.x;

    double s = 0.0;
    for (int i = tid; i < EPI_BLOCKS; i += 256) s += g_part[i];
    sh[tid] = s;

    double ent = 0.0;
    for (int i = tid; i < N_CODES; i += 256) {
        double p = (double)g_hist[i] * (1.0 / (double)M_ROWS);
        ent -= p * log(p + 1e-10);
    }
    sh2[tid] = ent;
    __syncthreads();

    for (int st = 128; st; st >>= 1) {
        if (tid < st) { sh[tid] += sh[tid + st]; sh2[tid] += sh2[tid + st]; }
        __syncthreads();
    }
    if (tid == 0) {
        double mse = sh[0] / ((double)M_ROWS * (double)K_DIM);
        out[0]        = (float)(1.25 * mse);
        out[OFF_PERP] = (float)exp(sh2[0]);
    }
}

// ============================================================
extern "C" void kernel_launch(void* const* d_in, const int* in_sizes, int n_in,
                              void* d_out, int out_size) {
    const float* X  = (const float*)d_in[0];
    const float* CB = (const float*)d_in[1];
    float* out = (float*)d_out;

    const int smem_p1 = 2 * 128 * PITCH * 2 + 128 * 8;  // 136192 bytes
    cudaFuncSetAttribute(vq_phase1,
                         cudaFuncAttributeMaxDynamicSharedMemorySize, smem_p1);

    vq_init<<<8, 256>>>(CB);
    vq_xnorm<<<M_ROWS / 256, 256>>>(X);
    vq_phase1<<<M_ROWS / 128, 256, smem_p1>>>(X);
    vq_phase2<<<M_ROWS / 8, 256>>>(X, CB);
    vq_epilogue<<<EPI_BLOCKS, 256>>>(X, CB, out);
    vq_finalize<<<1, 256>>>(out);
}